// round 11
// baseline (speedup 1.0000x reference)
#include <cuda_runtime.h>
#include <math.h>

// StandardTRM fused fp32 kernel.
// Tile = 64 rows, 256 threads, thread microtile = 8x8, warp w owns rows 8w..8w+7.
// z,y,h tiles live in SMEM for the whole 18-layer + 3-combine chain.
// Weights streamed from L2 via double-buffered cp.async slabs (8 rows x 256 cols).
// Inner product uses packed fma.rn.f32x2 (2 FMAs/lane/instr).

#define MT   64          // rows per CTA tile
#define LDA  260         // padded row stride (floats) for SMEM tiles
#define KS   8           // K rows per weight slab
#define LN_EPS_F 1e-5f

typedef unsigned long long u64;

__device__ __forceinline__ u64 pk2(float x, float y){
  u64 r; asm("mov.b64 %0, {%1, %2};" : "=l"(r) : "f"(x), "f"(y)); return r;
}
__device__ __forceinline__ void upk2(u64 v, float& x, float& y){
  asm("mov.b64 {%0, %1}, %2;" : "=f"(x), "=f"(y) : "l"(v));
}
__device__ __forceinline__ void fma2(u64& c, u64 a, u64 b){
  asm("fma.rn.f32x2 %0, %1, %2, %0;" : "+l"(c) : "l"(a), "l"(b));
}
__device__ __forceinline__ void cp16(float* s, const float* g){
  unsigned a = (unsigned)__cvta_generic_to_shared(s);
  asm volatile("cp.async.cg.shared.global [%0], [%1], 16;" :: "r"(a), "l"(g));
}
__device__ __forceinline__ void cpcommit(){ asm volatile("cp.async.commit_group;" ::: "memory"); }
__device__ __forceinline__ void cpwait0(){ asm volatile("cp.async.wait_group 0;" ::: "memory"); }

__device__ __forceinline__ float gelu_exact(float v){
  return 0.5f * v * (1.0f + erff(v * 0.7071067811865475f));
}

#define UNPACK8(ACC, I, C) do {                         \
    upk2((ACC)[(I)*4+0], (C)[0], (C)[1]);               \
    upk2((ACC)[(I)*4+1], (C)[2], (C)[3]);               \
    upk2((ACC)[(I)*4+2], (C)[4], (C)[5]);               \
    upk2((ACC)[(I)*4+3], (C)[6], (C)[7]);               \
  } while(0)

// acc[64,256] (+)= sA[64, K=256] @ W[256 x 256cols], W row stride = ldw floats.
// acc: 32 u64 (f32x2) per thread: acc[i*4+j] = cols (tx*8+2j, +1), row ty*8+i.
__device__ __forceinline__ void mm256(u64* __restrict__ acc,
                                      const float* __restrict__ sA,
                                      const float* __restrict__ gW, int ldw,
                                      float* __restrict__ sW,
                                      int tid, int ty, int tx)
{
  const int e  = tid * 8;      // this thread's 8-float chunk within an 8x256 slab
  const int er = e >> 8;
  const int ec = e & 255;
  // prefetch slab 0 into buffer 0
  {
    const float* src = gW + er * ldw + ec;
    cp16(sW + e,     src);
    cp16(sW + e + 4, src + 4);
    cpcommit();
  }
  const float* Abase = sA + ty * 8 * LDA;
  const int wcol = tx * 8;

  for (int s = 0; s < 32; ++s){
    cpwait0();
    __syncthreads();
    if (s < 31){
      float* dst = sW + ((s + 1) & 1) * (KS * 256);
      const float* src = gW + (s + 1) * KS * ldw + er * ldw + ec;
      cp16(dst + e,     src);
      cp16(dst + e + 4, src + 4);
      cpcommit();
    }
    const float* w = sW + (s & 1) * (KS * 256) + wcol;
    const float* A = Abase + s * KS;
#pragma unroll
    for (int k4 = 0; k4 < KS; k4 += 4){
      float4 av[8];
#pragma unroll
      for (int i = 0; i < 8; ++i)
        av[i] = *(const float4*)(A + i * LDA + k4);
#pragma unroll
      for (int t = 0; t < 4; ++t){
        const float* wr = w + (k4 + t) * 256;
        float4 b0 = *(const float4*)(wr);
        float4 b1 = *(const float4*)(wr + 4);
        u64 bb0 = pk2(b0.x, b0.y), bb1 = pk2(b0.z, b0.w);
        u64 bb2 = pk2(b1.x, b1.y), bb3 = pk2(b1.z, b1.w);
#pragma unroll
        for (int i = 0; i < 8; ++i){
          float a = (t == 0) ? av[i].x : (t == 1) ? av[i].y : (t == 2) ? av[i].z : av[i].w;
          u64 a2 = pk2(a, a);
          fma2(acc[i*4+0], a2, bb0);
          fma2(acc[i*4+1], a2, bb1);
          fma2(acc[i*4+2], a2, bb2);
          fma2(acc[i*4+3], a2, bb3);
        }
      }
    }
  }
}

__global__ void __launch_bounds__(256, 1)
trm_fused_kernel(const float* __restrict__ x,
                 const float* __restrict__ W_in,   const float* __restrict__ b_in,
                 const float* __restrict__ y_init,
                 const float* __restrict__ W_up,   const float* __restrict__ b_up,
                 const float* __restrict__ W_down, const float* __restrict__ b_down,
                 const float* __restrict__ ln_w,   const float* __restrict__ ln_b,
                 const float* __restrict__ W_comb, const float* __restrict__ b_comb,
                 const float* __restrict__ W_yt,   const float* __restrict__ b_yt,
                 const float* __restrict__ W_head, const float* __restrict__ b_head,
                 float* __restrict__ out)
{
  extern __shared__ float sm[];
  float* sZ = sm;                 // [64][260]
  float* sY = sZ + MT * LDA;      // [64][260]
  float* sH = sY + MT * LDA;      // [64][260]
  float* sW = sH + MT * LDA;      // 2 slabs of [8][256]

  const int tid = threadIdx.x;
  const int tx  = tid & 31;
  const int ty  = tid >> 5;
  const int n0  = tx * 8;
  const int r0  = blockIdx.x * MT;

  // ---- load x tile into sZ ----
  for (int e = tid * 4; e < MT * 256; e += 256 * 4){
    int r = e >> 8, c = e & 255;
    *(float4*)(sZ + r * LDA + c) = *(const float4*)(x + (size_t)(r0 + r) * 256 + c);
  }
  __syncthreads();

  // ---- z = x @ W_in + b_in ; y = y_init ----
  {
    u64 acc[32];
#pragma unroll
    for (int i = 0; i < 32; ++i) acc[i] = 0ull;
    mm256(acc, sZ, W_in, 256, sW, tid, ty, tx);
    __syncthreads();                    // all reads of sZ (x data) done before overwrite
    float bi[8], yv[8];
#pragma unroll
    for (int j = 0; j < 8; ++j){ bi[j] = b_in[n0 + j]; yv[j] = y_init[n0 + j]; }
#pragma unroll
    for (int i = 0; i < 8; ++i){
      float C[8]; UNPACK8(acc, i, C);
      float* zr = sZ + (ty * 8 + i) * LDA + n0;
      float* yr = sY + (ty * 8 + i) * LDA + n0;
#pragma unroll
      for (int j = 0; j < 8; ++j){ zr[j] = C[j] + bi[j]; yr[j] = yv[j]; }
    }
    __syncthreads();
  }

  // ---- 3 H-cycles ----
  for (int hc = 0; hc < 3; ++hc){
    // ---- 6 L-cycles ----
    for (int lc = 0; lc < 6; ++lc){
      u64 accD[32];
#pragma unroll
      for (int i = 0; i < 32; ++i) accD[i] = 0ull;

      // h = gelu(z @ W_up + b_up) in 4 chunks of 256 cols; accD += h_chunk @ W_down_chunk
      for (int c = 0; c < 4; ++c){
        u64 accU[32];
#pragma unroll
        for (int i = 0; i < 32; ++i) accU[i] = 0ull;
        mm256(accU, sZ, W_up + c * 256, 1024, sW, tid, ty, tx);
        float bu[8];
#pragma unroll
        for (int j = 0; j < 8; ++j) bu[j] = b_up[c * 256 + n0 + j];
#pragma unroll
        for (int i = 0; i < 8; ++i){
          float C[8]; UNPACK8(accU, i, C);
          float* hr = sH + (ty * 8 + i) * LDA + n0;
#pragma unroll
          for (int j = 0; j < 8; ++j) hr[j] = gelu_exact(C[j] + bu[j]);
        }
        // down-proj chunk: first internal __syncthreads of mm256 orders the sH writes
        mm256(accD, sH, W_down + c * 256 * 256, 256, sW, tid, ty, tx);
      }

      // ---- residual + LayerNorm, write back to sZ ----
      __syncthreads();
      float bd[8], lw[8], lb[8];
#pragma unroll
      for (int j = 0; j < 8; ++j){
        bd[j] = b_down[n0 + j]; lw[j] = ln_w[n0 + j]; lb[j] = ln_b[n0 + j];
      }
      float T[8][8], ps[8], pq[8];
#pragma unroll
      for (int i = 0; i < 8; ++i){
        float C[8]; UNPACK8(accD, i, C);
        const float* zr = sZ + (ty * 8 + i) * LDA + n0;
        float s = 0.f, q = 0.f;
#pragma unroll
        for (int j = 0; j < 8; ++j){
          float v = zr[j] + C[j] + bd[j];
          T[i][j] = v; s += v; q += v * v;
        }
        ps[i] = s; pq[i] = q;
      }
#pragma unroll
      for (int off = 16; off > 0; off >>= 1){
#pragma unroll
        for (int i = 0; i < 8; ++i){
          ps[i] += __shfl_xor_sync(0xffffffffu, ps[i], off);
          pq[i] += __shfl_xor_sync(0xffffffffu, pq[i], off);
        }
      }
#pragma unroll
      for (int i = 0; i < 8; ++i){
        float mu  = ps[i] * (1.0f / 256.0f);
        float var = pq[i] * (1.0f / 256.0f) - mu * mu;
        float rs  = rsqrtf(var + LN_EPS_F);
        float* zr = sZ + (ty * 8 + i) * LDA + n0;
#pragma unroll
        for (int j = 0; j < 8; ++j)
          zr[j] = (T[i][j] - mu) * rs * lw[j] + lb[j];
      }
      __syncthreads();
    }

    // ---- combine: h = gelu([z|y] @ W_comb + b_comb); y += h @ W_yt + b_yt ----
    {
      u64 acc[32];
#pragma unroll
      for (int i = 0; i < 32; ++i) acc[i] = 0ull;
      mm256(acc, sZ, W_comb,             256, sW, tid, ty, tx);
      mm256(acc, sY, W_comb + 256 * 256, 256, sW, tid, ty, tx);
      float bc[8];
#pragma unroll
      for (int j = 0; j < 8; ++j) bc[j] = b_comb[n0 + j];
#pragma unroll
      for (int i = 0; i < 8; ++i){
        float C[8]; UNPACK8(acc, i, C);
        float* hr = sH + (ty * 8 + i) * LDA + n0;
#pragma unroll
        for (int j = 0; j < 8; ++j) hr[j] = gelu_exact(C[j] + bc[j]);
      }
      u64 acc2[32];
#pragma unroll
      for (int i = 0; i < 32; ++i) acc2[i] = 0ull;
      mm256(acc2, sH, W_yt, 256, sW, tid, ty, tx);
      __syncthreads();
      float by[8];
#pragma unroll
      for (int j = 0; j < 8; ++j) by[j] = b_yt[n0 + j];
#pragma unroll
      for (int i = 0; i < 8; ++i){
        float C[8]; UNPACK8(acc2, i, C);
        float* yr = sY + (ty * 8 + i) * LDA + n0;
#pragma unroll
        for (int j = 0; j < 8; ++j) yr[j] += C[j] + by[j];
      }
      __syncthreads();
    }
  }

  // ---- head: out = y @ W_head + b_head  (N=10) ----
  __syncthreads();
  for (int e = tid; e < MT * 10; e += 256){
    int m = e / 10;
    int n = e - m * 10;
    float s = b_head[n];
    const float* yr = sY + m * LDA;
    for (int k = 0; k < 256; ++k)
      s += yr[k] * W_head[k * 10 + n];
    out[(size_t)(r0 + m) * 10 + n] = s;
  }
}

extern "C" void kernel_launch(void* const* d_in, const int* in_sizes, int n_in,
                              void* d_out, int out_size)
{
  const float* x      = (const float*)d_in[0];
  const float* W_in   = (const float*)d_in[1];
  const float* b_in   = (const float*)d_in[2];
  const float* y_init = (const float*)d_in[3];
  const float* W_up   = (const float*)d_in[4];
  const float* b_up   = (const float*)d_in[5];
  const float* W_down = (const float*)d_in[6];
  const float* b_down = (const float*)d_in[7];
  const float* ln_w   = (const float*)d_in[8];
  const float* ln_b   = (const float*)d_in[9];
  const float* W_comb = (const float*)d_in[10];
  const float* b_comb = (const float*)d_in[11];
  const float* W_yt   = (const float*)d_in[12];
  const float* b_yt   = (const float*)d_in[13];
  const float* W_head = (const float*)d_in[14];
  const float* b_head = (const float*)d_in[15];
  float* out = (float*)d_out;

  const int B = in_sizes[0] / 256;           // rows
  const size_t smem = (size_t)(3 * MT * LDA + 2 * KS * 256) * sizeof(float); // 216064 B

  cudaFuncSetAttribute(trm_fused_kernel,
                       cudaFuncAttributeMaxDynamicSharedMemorySize, (int)smem);

  trm_fused_kernel<<<B / MT, 256, smem>>>(
      x, W_in, b_in, y_init, W_up, b_up, W_down, b_down,
      ln_w, ln_b, W_comb, b_comb, W_yt, b_yt, W_head, b_head, out);
}